// round 15
// baseline (speedup 1.0000x reference)
#include <cuda_runtime.h>
#include <math.h>

#define BB 8
#define SS 2048
#define HH 1024
#define NN 262144
#define DD 512
#define KK 8
#define TKB 128

__device__ float g_xpart[32 * BB * HH];     // [z32][b][h], 1MB
__device__ float g_q[BB * DD];
__device__ float g_scores[BB * NN];
__device__ float g_cand_v[BB * TKB * 8];
__device__ int   g_cand_i[BB * TKB * 8];
__device__ float g_Rt[BB * DD * KK];
__device__ float g_W2[BB * KK * HH];        // [b][k][h] = (Wq @ R^T)^T * 1/sqrt(D)
__device__ float g_RO[BB * KK * HH];        // [b][k][h] = (R @ Wo) k-major

__device__ __forceinline__ void fma2(unsigned long long& d,
                                     unsigned long long a, unsigned long long b) {
    asm("fma.rn.f32x2 %0, %1, %2, %0;" : "+l"(d) : "l"(a), "l"(b));
}
__device__ __forceinline__ void unpack2(unsigned long long v, float& lo, float& hi) {
    unsigned int l, h;
    asm("mov.b64 {%0, %1}, %2;" : "=r"(l), "=r"(h) : "l"(v));
    lo = __uint_as_float(l); hi = __uint_as_float(h);
}
__device__ __forceinline__ unsigned long long pack2(float lo, float hi) {
    unsigned long long r;
    asm("mov.b64 %0, {%1, %2};" : "=l"(r)
        : "r"(__float_as_uint(lo)), "r"(__float_as_uint(hi)));
    return r;
}

// ---------- Kernel A: partial sums of x over S (float4, 32 slots x 64 rows) ----------
__global__ void __launch_bounds__(256) k_xpart4(const float* __restrict__ x) {
    int h4 = threadIdx.x;
    int b = blockIdx.y;
    int z = blockIdx.z;                       // 32 slots of 64 rows
    const float4* xp = (const float4*)x + ((size_t)b * SS + (size_t)z * 64) * 256 + h4;
    float4 a0 = make_float4(0.f, 0.f, 0.f, 0.f), a1 = a0, a2 = a0, a3 = a0;
    float4 a4 = a0, a5 = a0, a6 = a0, a7 = a0;
#pragma unroll 4
    for (int i = 0; i < 64; i += 8) {
        float4 v0 = xp[(size_t)(i + 0) * 256];
        float4 v1 = xp[(size_t)(i + 1) * 256];
        float4 v2 = xp[(size_t)(i + 2) * 256];
        float4 v3 = xp[(size_t)(i + 3) * 256];
        float4 v4 = xp[(size_t)(i + 4) * 256];
        float4 v5 = xp[(size_t)(i + 5) * 256];
        float4 v6 = xp[(size_t)(i + 6) * 256];
        float4 v7 = xp[(size_t)(i + 7) * 256];
        a0.x += v0.x; a0.y += v0.y; a0.z += v0.z; a0.w += v0.w;
        a1.x += v1.x; a1.y += v1.y; a1.z += v1.z; a1.w += v1.w;
        a2.x += v2.x; a2.y += v2.y; a2.z += v2.z; a2.w += v2.w;
        a3.x += v3.x; a3.y += v3.y; a3.z += v3.z; a3.w += v3.w;
        a4.x += v4.x; a4.y += v4.y; a4.z += v4.z; a4.w += v4.w;
        a5.x += v5.x; a5.y += v5.y; a5.z += v5.z; a5.w += v5.w;
        a6.x += v6.x; a6.y += v6.y; a6.z += v6.z; a6.w += v6.w;
        a7.x += v7.x; a7.y += v7.y; a7.z += v7.z; a7.w += v7.w;
    }
    float4 r;
    r.x = ((a0.x + a1.x) + (a2.x + a3.x)) + ((a4.x + a5.x) + (a6.x + a7.x));
    r.y = ((a0.y + a1.y) + (a2.y + a3.y)) + ((a4.y + a5.y) + (a6.y + a7.y));
    r.z = ((a0.z + a1.z) + (a2.z + a3.z)) + ((a4.z + a5.z) + (a6.z + a7.z));
    r.w = ((a0.w + a1.w) + (a2.w + a3.w)) + ((a4.w + a5.w) + (a6.w + a7.w));
    ((float4*)g_xpart)[(z * BB + b) * 256 + h4] = r;
}

// ---------- Kernel B (fused): q[b][d] = (sum_z xpart) @ Wq ----------
__global__ void __launch_bounds__(256) k_query(const float* __restrict__ Wq) {
    __shared__ float xs[HH];
    int tid = threadIdx.x;
    int b = blockIdx.y;
    for (int h = tid; h < HH; h += 256) {
        float s = 0.0f;
#pragma unroll 8
        for (int z = 0; z < 32; z++)
            s += g_xpart[(z * BB + b) * HH + h];
        xs[h] = s;
    }
    __syncthreads();

    int d = blockIdx.x * 256 + tid;          // grid.x = 2
    float a0 = 0.f, a1 = 0.f, a2 = 0.f, a3 = 0.f, a4 = 0.f, a5 = 0.f, a6 = 0.f, a7 = 0.f;
    const float* wq = Wq + d;
#pragma unroll 4
    for (int h = 0; h < HH; h += 8) {
        a0 += xs[h + 0] * wq[(size_t)(h + 0) * DD];
        a1 += xs[h + 1] * wq[(size_t)(h + 1) * DD];
        a2 += xs[h + 2] * wq[(size_t)(h + 2) * DD];
        a3 += xs[h + 3] * wq[(size_t)(h + 3) * DD];
        a4 += xs[h + 4] * wq[(size_t)(h + 4) * DD];
        a5 += xs[h + 5] * wq[(size_t)(h + 5) * DD];
        a6 += xs[h + 6] * wq[(size_t)(h + 6) * DD];
        a7 += xs[h + 7] * wq[(size_t)(h + 7) * DD];
    }
    g_q[b * DD + d] = ((a0 + a1) + (a2 + a3)) + ((a4 + a5) + (a6 + a7));
}

// ---------- Kernel C: cosine scores (R12-exact: measured 109.3-109.7us) ----------
__global__ void __launch_bounds__(256, 3) k_scores(const float* __restrict__ mem) {
    __shared__ ulonglong2 qd[BB * 128];   // [b][d4], 16KB
    __shared__ float s_out[BB * 64];      // 2KB
    int tid = threadIdx.x;
    {
        const ulonglong2* q2 = (const ulonglong2*)g_q;
        for (int i = tid; i < BB * 128; i += 256) qd[i] = q2[i];
    }
    __syncthreads();

    int w = tid >> 5, lane = tid & 31;
    int g = lane >> 3, e = lane & 7;
    int rowloc = w * 8 + g * 2;
    size_t row0 = (size_t)blockIdx.x * 64 + rowloc;
    const ulonglong2* ma_p = (const ulonglong2*)(mem + row0 * DD);
    const ulonglong2* mb_p = (const ulonglong2*)(mem + (row0 + 1) * DD);

    unsigned long long acc2[2][8];
    unsigned long long nrm2[2];
    nrm2[0] = nrm2[1] = 0ull;
#pragma unroll
    for (int b = 0; b < 8; b++) { acc2[0][b] = 0ull; acc2[1][b] = 0ull; }

#pragma unroll 2
    for (int j = 0; j < 16; j++) {
        int d4 = e + 8 * j;
        ulonglong2 ma = ma_p[d4];
        ulonglong2 mb = mb_p[d4];

        fma2(nrm2[0], ma.x, ma.x);
        fma2(nrm2[0], ma.y, ma.y);
        fma2(nrm2[1], mb.x, mb.x);
        fma2(nrm2[1], mb.y, mb.y);
#pragma unroll
        for (int b = 0; b < 8; b++) {
            ulonglong2 qv = qd[b * 128 + d4];
            fma2(acc2[0][b], ma.x, qv.x);
            fma2(acc2[0][b], ma.y, qv.y);
            fma2(acc2[1][b], mb.x, qv.x);
            fma2(acc2[1][b], mb.y, qv.y);
        }
    }

    float acc[2][8], nrm[2];
#pragma unroll
    for (int r = 0; r < 2; r++) {
        float lo, hi;
        unpack2(nrm2[r], lo, hi);
        nrm[r] = lo + hi;
#pragma unroll
        for (int b = 0; b < 8; b++) {
            unpack2(acc2[r][b], lo, hi);
            acc[r][b] = lo + hi;
        }
    }
#pragma unroll
    for (int off = 1; off <= 4; off <<= 1) {
#pragma unroll
        for (int r = 0; r < 2; r++) {
            nrm[r] += __shfl_xor_sync(0xffffffffu, nrm[r], off);
#pragma unroll
            for (int b = 0; b < 8; b++)
                acc[r][b] += __shfl_xor_sync(0xffffffffu, acc[r][b], off);
        }
    }
    if (e == 0) {
#pragma unroll
        for (int r = 0; r < 2; r++) {
            float inv = 1.0f / (sqrtf(nrm[r]) + 1e-8f);
#pragma unroll
            for (int b = 0; b < 8; b++)
                s_out[b * 64 + rowloc + r] = acc[r][b] * inv;
        }
    }
    __syncthreads();
    if (tid < 128) {
        int b = tid >> 4, seg = tid & 15;
        *(float4*)&g_scores[(size_t)b * NN + (size_t)blockIdx.x * 64 + seg * 4] =
            *(const float4*)&s_out[b * 64 + seg * 4];
    }
}

// ---------- Kernel D1: stage-1 top-8 (NOW IN THE NCU CAPTURE SLOT) ----------
__global__ void __launch_bounds__(256) k_topk1() {
    __shared__ float sv[256 * 8];
    __shared__ int   si[256 * 8];
    int b = blockIdx.y, blk = blockIdx.x, tid = threadIdx.x;
    int base = blk * (NN / TKB);
    const float4* s4 = (const float4*)(g_scores + (size_t)b * NN + base);

    float vals[8];
    int idxs[8];
#pragma unroll
    for (int i = 0; i < 8; i++) { vals[i] = -3.4e38f; idxs[i] = 0; }
    float vmin = -3.4e38f;

#pragma unroll
    for (int it = 0; it < 2; it++) {
        int f = tid + it * 256;
        float4 v4 = s4[f];
        int n0 = base + f * 4;
        float vv[4] = {v4.x, v4.y, v4.z, v4.w};
#pragma unroll
        for (int c = 0; c < 4; c++) {
            float v = vv[c];
            if (v > vmin) {
                vals[7] = v; idxs[7] = n0 + c;
#pragma unroll
                for (int p = 7; p >= 1; p--) {
                    if (vals[p] > vals[p - 1]) {
                        float tv = vals[p]; vals[p] = vals[p - 1]; vals[p - 1] = tv;
                        int ti = idxs[p]; idxs[p] = idxs[p - 1]; idxs[p - 1] = ti;
                    }
                }
                vmin = vals[7];
            }
        }
    }
#pragma unroll
    for (int i = 0; i < 8; i++) { sv[tid * 8 + i] = vals[i]; si[tid * 8 + i] = idxs[i]; }

    for (int stride = 128; stride >= 1; stride >>= 1) {
        __syncthreads();
        if (tid < stride) {
            float ov[8]; int oi[8];
            int ia = 0, ib2 = 0;
#pragma unroll
            for (int o = 0; o < 8; o++) {
                float va = sv[tid * 8 + ia];
                float vb = sv[(tid + stride) * 8 + ib2];
                if (va >= vb) { ov[o] = va; oi[o] = si[tid * 8 + ia]; ia++; }
                else          { ov[o] = vb; oi[o] = si[(tid + stride) * 8 + ib2]; ib2++; }
            }
#pragma unroll
            for (int o = 0; o < 8; o++) { sv[tid * 8 + o] = ov[o]; si[tid * 8 + o] = oi[o]; }
        }
    }
    __syncthreads();
    if (tid < 8) {
        g_cand_v[(b * TKB + blk) * 8 + tid] = sv[tid];
        g_cand_i[(b * TKB + blk) * 8 + tid] = si[tid];
    }
}

// ---------- Kernel D2+E1 fused: final merge + gather + normalize ----------
__global__ void __launch_bounds__(128) k_finish(const float* __restrict__ mem) {
    __shared__ float sv[128 * 8];
    __shared__ int   si[128 * 8];
    __shared__ int   s_idx[8];
    int b = blockIdx.x, tid = threadIdx.x;
#pragma unroll
    for (int i = 0; i < 8; i++) {
        sv[tid * 8 + i] = g_cand_v[(b * TKB + tid) * 8 + i];
        si[tid * 8 + i] = g_cand_i[(b * TKB + tid) * 8 + i];
    }
    for (int stride = 64; stride >= 1; stride >>= 1) {
        __syncthreads();
        if (tid < stride) {
            float ov[8]; int oi[8];
            int ia = 0, ib2 = 0;
#pragma unroll
            for (int o = 0; o < 8; o++) {
                float va = sv[tid * 8 + ia];
                float vb = sv[(tid + stride) * 8 + ib2];
                if (va >= vb) { ov[o] = va; oi[o] = si[tid * 8 + ia]; ia++; }
                else          { ov[o] = vb; oi[o] = si[(tid + stride) * 8 + ib2]; ib2++; }
            }
#pragma unroll
            for (int o = 0; o < 8; o++) { sv[tid * 8 + o] = ov[o]; si[tid * 8 + o] = oi[o]; }
        }
    }
    __syncthreads();
    if (tid < 8) s_idx[tid] = si[tid];
    __syncthreads();

    int w = tid >> 5, lane = tid & 31;
#pragma unroll
    for (int kk = 0; kk < 2; kk++) {
        int k = w * 2 + kk;
        int row = s_idx[k];
        const float4* r4 = (const float4*)(mem + (size_t)row * DD);
        float4 v[4];
        float nr = 0.0f;
#pragma unroll
        for (int jj = 0; jj < 4; jj++) {
            v[jj] = r4[lane + 32 * jj];
            nr += v[jj].x * v[jj].x + v[jj].y * v[jj].y
                + v[jj].z * v[jj].z + v[jj].w * v[jj].w;
        }
#pragma unroll
        for (int off = 16; off; off >>= 1)
            nr += __shfl_xor_sync(0xffffffffu, nr, off);
        float inv = 1.0f / (sqrtf(nr) + 1e-8f);
        float* Rt = g_Rt + (size_t)b * DD * 8;
#pragma unroll
        for (int jj = 0; jj < 4; jj++) {
            int d0 = (lane + 32 * jj) * 4;
            Rt[(d0 + 0) * 8 + k] = v[jj].x * inv;
            Rt[(d0 + 1) * 8 + k] = v[jj].y * inv;
            Rt[(d0 + 2) * 8 + k] = v[jj].z * inv;
            Rt[(d0 + 3) * 8 + k] = v[jj].w * inv;
        }
    }
}

// ---------- Kernel E2+E3 fused: outputs k-major [b][k][h] (R13 config) ----------
__global__ void __launch_bounds__(256) k_w2ro(const float* __restrict__ Wq,
                                              const float* __restrict__ Wo) {
    __shared__ float4 R_sh[DD * 2];
    int b = blockIdx.y;
    const float4* Rt4 = (const float4*)(g_Rt + (size_t)b * DD * 8);
    for (int i = threadIdx.x; i < DD * 2; i += 256) R_sh[i] = Rt4[i];
    __syncthreads();

    int h = blockIdx.x * 256 + threadIdx.x;  // grid.x = 4
    float acc[8];
#pragma unroll
    for (int k = 0; k < 8; k++) acc[k] = 0.0f;

    if (blockIdx.z == 0) {
        const float4* wq4 = (const float4*)(Wq + (size_t)h * DD);
#pragma unroll 2
        for (int dd = 0; dd < DD / 4; dd++) {
            float4 wv4 = wq4[dd];
            float wv[4] = {wv4.x, wv4.y, wv4.z, wv4.w};
#pragma unroll
            for (int c = 0; c < 4; c++) {
                float4 r0 = R_sh[(dd * 4 + c) * 2];
                float4 r1 = R_sh[(dd * 4 + c) * 2 + 1];
                acc[0] += wv[c] * r0.x; acc[1] += wv[c] * r0.y;
                acc[2] += wv[c] * r0.z; acc[3] += wv[c] * r0.w;
                acc[4] += wv[c] * r1.x; acc[5] += wv[c] * r1.y;
                acc[6] += wv[c] * r1.z; acc[7] += wv[c] * r1.w;
            }
        }
        const float scale = 0.044194173824159216f;  // 1/sqrt(512)
#pragma unroll
        for (int k = 0; k < 8; k++)
            g_W2[((size_t)b * KK + k) * HH + h] = acc[k] * scale;
    } else {
#pragma unroll 4
        for (int d = 0; d < DD; d++) {
            float wo = Wo[(size_t)d * HH + h];
            float4 r0 = R_sh[d * 2];
            float4 r1 = R_sh[d * 2 + 1];
            acc[0] += wo * r0.x; acc[1] += wo * r0.y; acc[2] += wo * r0.z; acc[3] += wo * r0.w;
            acc[4] += wo * r1.x; acc[5] += wo * r1.y; acc[6] += wo * r1.z; acc[7] += wo * r1.w;
        }
#pragma unroll
        for (int k = 0; k < 8; k++)
            g_RO[((size_t)b * KK + k) * HH + h] = acc[k];
    }
}

// ---------- Kernel F (fused, f32x2): logits -> softmax -> out ----------
__global__ void __launch_bounds__(256) k_attn_out(const float* __restrict__ x,
                                                  float* __restrict__ out) {
    __shared__ float W2s[KK * HH];   // 32KB, [k][h]
    int b = blockIdx.y;
    {
        const float4* src = (const float4*)(g_W2 + (size_t)b * KK * HH);
        float4* dst = (float4*)W2s;
        for (int i = threadIdx.x; i < KK * HH / 4; i += 256) dst[i] = src[i];
    }
    __syncthreads();

    int lane = threadIdx.x & 31, warp = threadIdx.x >> 5;
    int tok0 = blockIdx.x * 16 + warp * 2;
    const ulonglong2* xb0 = (const ulonglong2*)(x + ((size_t)b * SS + tok0) * HH);
    const ulonglong2* xb1 = xb0 + HH / 4;
    const ulonglong2* W2s2 = (const ulonglong2*)W2s;

    unsigned long long acc2[2][8];
#pragma unroll
    for (int k = 0; k < 8; k++) { acc2[0][k] = 0ull; acc2[1][k] = 0ull; }

#pragma unroll 2
    for (int i4 = 0; i4 < 8; i4++) {
        int h4 = lane + 32 * i4;
        ulonglong2 x0 = xb0[h4];
        ulonglong2 x1 = xb1[h4];
#pragma unroll
        for (int k = 0; k < 8; k++) {
            ulonglong2 wv = W2s2[k * (HH / 4) + h4];
            fma2(acc2[0][k], x0.x, wv.x);
            fma2(acc2[0][k], x0.y, wv.y);
            fma2(acc2[1][k], x1.x, wv.x);
            fma2(acc2[1][k], x1.y, wv.y);
        }
    }

    float lp[2][8];
#pragma unroll
    for (int t = 0; t < 2; t++)
#pragma unroll
        for (int k = 0; k < 8; k++) {
            float lo, hi;
            unpack2(acc2[t][k], lo, hi);
            lp[t][k] = lo + hi;
        }
#pragma unroll
    for (int off = 16; off; off >>= 1)
#pragma unroll
        for (int t = 0; t < 2; t++)
#pragma unroll
            for (int k = 0; k < 8; k++)
                lp[t][k] += __shfl_xor_sync(0xffffffffu, lp[t][k], off);

    unsigned long long att2[2][8];
#pragma unroll
    for (int t = 0; t < 2; t++) {
        float m = -3.4e38f;
#pragma unroll
        for (int k = 0; k < 8; k++) m = fmaxf(m, lp[t][k]);
        float s = 0.0f;
        float e[8];
#pragma unroll
        for (int k = 0; k < 8; k++) { e[k] = __expf(lp[t][k] - m); s += e[k]; }
        float inv = 1.0f / s;
#pragma unroll
        for (int k = 0; k < 8; k++) {
            float a = e[k] * inv;
            att2[t][k] = pack2(a, a);
        }
    }

    const ulonglong2* ROb = (const ulonglong2*)(g_RO + (size_t)b * KK * HH);
    ulonglong2* ob0 = (ulonglong2*)(out + ((size_t)b * SS + tok0) * HH);
    ulonglong2* ob1 = ob0 + HH / 4;

#pragma unroll 2
    for (int i4 = 0; i4 < 8; i4++) {
        int h4 = lane + 32 * i4;
        ulonglong2 o0 = xb0[h4];
        ulonglong2 o1 = xb1[h4];
#pragma unroll
        for (int k = 0; k < 8; k++) {
            ulonglong2 rv = __ldg(&ROb[k * (HH / 4) + h4]);
            fma2(o0.x, att2[0][k], rv.x);
            fma2(o0.y, att2[0][k], rv.y);
            fma2(o1.x, att2[1][k], rv.x);
            fma2(o1.y, att2[1][k], rv.y);
        }
        ob0[h4] = o0;
        ob1[h4] = o1;
    }
}

// ---------- launch (topk1 = 4th launch -> ncu capture rotates to the tail) ----------
extern "C" void kernel_launch(void* const* d_in, const int* in_sizes, int n_in,
                              void* d_out, int out_size) {
    const float* x   = (const float*)d_in[0];
    const float* mem = (const float*)d_in[1];
    const float* Wq  = (const float*)d_in[2];
    const float* Wo  = (const float*)d_in[3];
    float* out = (float*)d_out;

    k_xpart4  <<<dim3(1, 8, 32), 256>>>(x);
    k_query   <<<dim3(2, 8),     256>>>(Wq);
    k_scores  <<<4096,           256>>>(mem);
    k_topk1   <<<dim3(TKB, 8),   256>>>();
    k_finish  <<<8,              128>>>(mem);
    k_w2ro    <<<dim3(4, 8, 2),  256>>>(Wq, Wo);
    k_attn_out<<<dim3(128, 8),   256>>>(x, out);
}

// round 16
// speedup vs baseline: 1.1778x; 1.1778x over previous
#include <cuda_runtime.h>
#include <math.h>

#define BB 8
#define SS 2048
#define HH 1024
#define NN 262144
#define DD 512
#define KK 8
#define TKB 128

__device__ float g_xpart[32 * BB * HH];     // [z32][b][h], 1MB
__device__ float g_qp[8 * BB * DD];         // [hc][b][d] partial queries
__device__ float g_q[BB * DD];
__device__ float g_scores[BB * NN];
__device__ float g_cand_v[BB * TKB * 8];
__device__ int   g_cand_i[BB * TKB * 8];
__device__ float g_Rt[BB * DD * KK];
__device__ float g_W2[BB * KK * HH];        // [b][k][h] = (Wq @ R^T)^T * 1/sqrt(D)
__device__ float g_RO[BB * KK * HH];        // [b][k][h] = (R @ Wo) k-major

__device__ __forceinline__ void fma2(unsigned long long& d,
                                     unsigned long long a, unsigned long long b) {
    asm("fma.rn.f32x2 %0, %1, %2, %0;" : "+l"(d) : "l"(a), "l"(b));
}
__device__ __forceinline__ void unpack2(unsigned long long v, float& lo, float& hi) {
    unsigned int l, h;
    asm("mov.b64 {%0, %1}, %2;" : "=r"(l), "=r"(h) : "l"(v));
    lo = __uint_as_float(l); hi = __uint_as_float(h);
}
__device__ __forceinline__ unsigned long long pack2(float lo, float hi) {
    unsigned long long r;
    asm("mov.b64 %0, {%1, %2};" : "=l"(r)
        : "r"(__float_as_uint(lo)), "r"(__float_as_uint(hi)));
    return r;
}

// ---------- Kernel A: partial sums of x over S (float4, 32 slots x 64 rows) ----------
__global__ void __launch_bounds__(256) k_xpart4(const float* __restrict__ x) {
    int h4 = threadIdx.x;
    int b = blockIdx.y;
    int z = blockIdx.z;
    const float4* xp = (const float4*)x + ((size_t)b * SS + (size_t)z * 64) * 256 + h4;
    float4 a0 = make_float4(0.f, 0.f, 0.f, 0.f), a1 = a0, a2 = a0, a3 = a0;
    float4 a4 = a0, a5 = a0, a6 = a0, a7 = a0;
#pragma unroll 4
    for (int i = 0; i < 64; i += 8) {
        float4 v0 = xp[(size_t)(i + 0) * 256];
        float4 v1 = xp[(size_t)(i + 1) * 256];
        float4 v2 = xp[(size_t)(i + 2) * 256];
        float4 v3 = xp[(size_t)(i + 3) * 256];
        float4 v4 = xp[(size_t)(i + 4) * 256];
        float4 v5 = xp[(size_t)(i + 5) * 256];
        float4 v6 = xp[(size_t)(i + 6) * 256];
        float4 v7 = xp[(size_t)(i + 7) * 256];
        a0.x += v0.x; a0.y += v0.y; a0.z += v0.z; a0.w += v0.w;
        a1.x += v1.x; a1.y += v1.y; a1.z += v1.z; a1.w += v1.w;
        a2.x += v2.x; a2.y += v2.y; a2.z += v2.z; a2.w += v2.w;
        a3.x += v3.x; a3.y += v3.y; a3.z += v3.z; a3.w += v3.w;
        a4.x += v4.x; a4.y += v4.y; a4.z += v4.z; a4.w += v4.w;
        a5.x += v5.x; a5.y += v5.y; a5.z += v5.z; a5.w += v5.w;
        a6.x += v6.x; a6.y += v6.y; a6.z += v6.z; a6.w += v6.w;
        a7.x += v7.x; a7.y += v7.y; a7.z += v7.z; a7.w += v7.w;
    }
    float4 r;
    r.x = ((a0.x + a1.x) + (a2.x + a3.x)) + ((a4.x + a5.x) + (a6.x + a7.x));
    r.y = ((a0.y + a1.y) + (a2.y + a3.y)) + ((a4.y + a5.y) + (a6.y + a7.y));
    r.z = ((a0.z + a1.z) + (a2.z + a3.z)) + ((a4.z + a5.z) + (a6.z + a7.z));
    r.w = ((a0.w + a1.w) + (a2.w + a3.w)) + ((a4.w + a5.w) + (a6.w + a7.w));
    ((float4*)g_xpart)[(z * BB + b) * 256 + h4] = r;
}

// ---------- Kernel B: partial q over 128-h chunks (128 blocks) ----------
__global__ void __launch_bounds__(256) k_queryp(const float* __restrict__ Wq) {
    __shared__ float xs[128];
    int tid = threadIdx.x;
    int b = blockIdx.y, hc = blockIdx.z;
    if (tid < 128) {
        float s = 0.0f;
#pragma unroll
        for (int z = 0; z < 32; z++)
            s += g_xpart[(z * BB + b) * HH + hc * 128 + tid];
        xs[tid] = s;
    }
    __syncthreads();

    int d = blockIdx.x * 256 + tid;
    float a0 = 0.f, a1 = 0.f, a2 = 0.f, a3 = 0.f, a4 = 0.f, a5 = 0.f, a6 = 0.f, a7 = 0.f;
    const float* wq = Wq + (size_t)(hc * 128) * DD + d;
#pragma unroll 4
    for (int h = 0; h < 128; h += 8) {
        a0 += xs[h + 0] * wq[(size_t)(h + 0) * DD];
        a1 += xs[h + 1] * wq[(size_t)(h + 1) * DD];
        a2 += xs[h + 2] * wq[(size_t)(h + 2) * DD];
        a3 += xs[h + 3] * wq[(size_t)(h + 3) * DD];
        a4 += xs[h + 4] * wq[(size_t)(h + 4) * DD];
        a5 += xs[h + 5] * wq[(size_t)(h + 5) * DD];
        a6 += xs[h + 6] * wq[(size_t)(h + 6) * DD];
        a7 += xs[h + 7] * wq[(size_t)(h + 7) * DD];
    }
    g_qp[(hc * BB + b) * DD + d] = ((a0 + a1) + (a2 + a3)) + ((a4 + a5) + (a6 + a7));
}

// ---------- Kernel B2: q = sum of 8 partials ----------
__global__ void k_qsum() {
    int i = blockIdx.x * 256 + threadIdx.x;
    float s = 0.0f;
#pragma unroll
    for (int hc = 0; hc < 8; hc++) s += g_qp[hc * BB * DD + i];
    g_q[i] = s;
}

// ---------- Kernel C: cosine scores (R12-exact: measured 109.3/109.7us) ----------
__global__ void __launch_bounds__(256, 3) k_scores(const float* __restrict__ mem) {
    __shared__ ulonglong2 qd[BB * 128];   // [b][d4], 16KB
    __shared__ float s_out[BB * 64];      // 2KB
    int tid = threadIdx.x;
    {
        const ulonglong2* q2 = (const ulonglong2*)g_q;
        for (int i = tid; i < BB * 128; i += 256) qd[i] = q2[i];
    }
    __syncthreads();

    int w = tid >> 5, lane = tid & 31;
    int g = lane >> 3, e = lane & 7;
    int rowloc = w * 8 + g * 2;
    size_t row0 = (size_t)blockIdx.x * 64 + rowloc;
    const ulonglong2* ma_p = (const ulonglong2*)(mem + row0 * DD);
    const ulonglong2* mb_p = (const ulonglong2*)(mem + (row0 + 1) * DD);

    unsigned long long acc2[2][8];
    unsigned long long nrm2[2];
    nrm2[0] = nrm2[1] = 0ull;
#pragma unroll
    for (int b = 0; b < 8; b++) { acc2[0][b] = 0ull; acc2[1][b] = 0ull; }

#pragma unroll 2
    for (int j = 0; j < 16; j++) {
        int d4 = e + 8 * j;
        ulonglong2 ma = ma_p[d4];
        ulonglong2 mb = mb_p[d4];

        fma2(nrm2[0], ma.x, ma.x);
        fma2(nrm2[0], ma.y, ma.y);
        fma2(nrm2[1], mb.x, mb.x);
        fma2(nrm2[1], mb.y, mb.y);
#pragma unroll
        for (int b = 0; b < 8; b++) {
            ulonglong2 qv = qd[b * 128 + d4];
            fma2(acc2[0][b], ma.x, qv.x);
            fma2(acc2[0][b], ma.y, qv.y);
            fma2(acc2[1][b], mb.x, qv.x);
            fma2(acc2[1][b], mb.y, qv.y);
        }
    }

    float acc[2][8], nrm[2];
#pragma unroll
    for (int r = 0; r < 2; r++) {
        float lo, hi;
        unpack2(nrm2[r], lo, hi);
        nrm[r] = lo + hi;
#pragma unroll
        for (int b = 0; b < 8; b++) {
            unpack2(acc2[r][b], lo, hi);
            acc[r][b] = lo + hi;
        }
    }
#pragma unroll
    for (int off = 1; off <= 4; off <<= 1) {
#pragma unroll
        for (int r = 0; r < 2; r++) {
            nrm[r] += __shfl_xor_sync(0xffffffffu, nrm[r], off);
#pragma unroll
            for (int b = 0; b < 8; b++)
                acc[r][b] += __shfl_xor_sync(0xffffffffu, acc[r][b], off);
        }
    }
    if (e == 0) {
#pragma unroll
        for (int r = 0; r < 2; r++) {
            float inv = 1.0f / (sqrtf(nrm[r]) + 1e-8f);
#pragma unroll
            for (int b = 0; b < 8; b++)
                s_out[b * 64 + rowloc + r] = acc[r][b] * inv;
        }
    }
    __syncthreads();
    if (tid < 128) {
        int b = tid >> 4, seg = tid & 15;
        *(float4*)&g_scores[(size_t)b * NN + (size_t)blockIdx.x * 64 + seg * 4] =
            *(const float4*)&s_out[b * 64 + seg * 4];
    }
}

// ---------- Kernel D1: stage-1 top-8 ----------
__global__ void __launch_bounds__(256) k_topk1() {
    __shared__ float sv[256 * 8];
    __shared__ int   si[256 * 8];
    int b = blockIdx.y, blk = blockIdx.x, tid = threadIdx.x;
    int base = blk * (NN / TKB);
    const float4* s4 = (const float4*)(g_scores + (size_t)b * NN + base);

    float vals[8];
    int idxs[8];
#pragma unroll
    for (int i = 0; i < 8; i++) { vals[i] = -3.4e38f; idxs[i] = 0; }
    float vmin = -3.4e38f;

#pragma unroll
    for (int it = 0; it < 2; it++) {
        int f = tid + it * 256;
        float4 v4 = s4[f];
        int n0 = base + f * 4;
        float vv[4] = {v4.x, v4.y, v4.z, v4.w};
#pragma unroll
        for (int c = 0; c < 4; c++) {
            float v = vv[c];
            if (v > vmin) {
                vals[7] = v; idxs[7] = n0 + c;
#pragma unroll
                for (int p = 7; p >= 1; p--) {
                    if (vals[p] > vals[p - 1]) {
                        float tv = vals[p]; vals[p] = vals[p - 1]; vals[p - 1] = tv;
                        int ti = idxs[p]; idxs[p] = idxs[p - 1]; idxs[p - 1] = ti;
                    }
                }
                vmin = vals[7];
            }
        }
    }
#pragma unroll
    for (int i = 0; i < 8; i++) { sv[tid * 8 + i] = vals[i]; si[tid * 8 + i] = idxs[i]; }

    for (int stride = 128; stride >= 1; stride >>= 1) {
        __syncthreads();
        if (tid < stride) {
            float ov[8]; int oi[8];
            int ia = 0, ib2 = 0;
#pragma unroll
            for (int o = 0; o < 8; o++) {
                float va = sv[tid * 8 + ia];
                float vb = sv[(tid + stride) * 8 + ib2];
                if (va >= vb) { ov[o] = va; oi[o] = si[tid * 8 + ia]; ia++; }
                else          { ov[o] = vb; oi[o] = si[(tid + stride) * 8 + ib2]; ib2++; }
            }
#pragma unroll
            for (int o = 0; o < 8; o++) { sv[tid * 8 + o] = ov[o]; si[tid * 8 + o] = oi[o]; }
        }
    }
    __syncthreads();
    if (tid < 8) {
        g_cand_v[(b * TKB + blk) * 8 + tid] = sv[tid];
        g_cand_i[(b * TKB + blk) * 8 + tid] = si[tid];
    }
}

// ---------- Kernel D2+E1 fused: final merge + gather + normalize ----------
__global__ void __launch_bounds__(128) k_finish(const float* __restrict__ mem) {
    __shared__ float sv[128 * 8];
    __shared__ int   si[128 * 8];
    __shared__ int   s_idx[8];
    int b = blockIdx.x, tid = threadIdx.x;
#pragma unroll
    for (int i = 0; i < 8; i++) {
        sv[tid * 8 + i] = g_cand_v[(b * TKB + tid) * 8 + i];
        si[tid * 8 + i] = g_cand_i[(b * TKB + tid) * 8 + i];
    }
    for (int stride = 64; stride >= 1; stride >>= 1) {
        __syncthreads();
        if (tid < stride) {
            float ov[8]; int oi[8];
            int ia = 0, ib2 = 0;
#pragma unroll
            for (int o = 0; o < 8; o++) {
                float va = sv[tid * 8 + ia];
                float vb = sv[(tid + stride) * 8 + ib2];
                if (va >= vb) { ov[o] = va; oi[o] = si[tid * 8 + ia]; ia++; }
                else          { ov[o] = vb; oi[o] = si[(tid + stride) * 8 + ib2]; ib2++; }
            }
#pragma unroll
            for (int o = 0; o < 8; o++) { sv[tid * 8 + o] = ov[o]; si[tid * 8 + o] = oi[o]; }
        }
    }
    __syncthreads();
    if (tid < 8) s_idx[tid] = si[tid];
    __syncthreads();

    int w = tid >> 5, lane = tid & 31;
#pragma unroll
    for (int kk = 0; kk < 2; kk++) {
        int k = w * 2 + kk;
        int row = s_idx[k];
        const float4* r4 = (const float4*)(mem + (size_t)row * DD);
        float4 v[4];
        float nr = 0.0f;
#pragma unroll
        for (int jj = 0; jj < 4; jj++) {
            v[jj] = r4[lane + 32 * jj];
            nr += v[jj].x * v[jj].x + v[jj].y * v[jj].y
                + v[jj].z * v[jj].z + v[jj].w * v[jj].w;
        }
#pragma unroll
        for (int off = 16; off; off >>= 1)
            nr += __shfl_xor_sync(0xffffffffu, nr, off);
        float inv = 1.0f / (sqrtf(nr) + 1e-8f);
        float* Rt = g_Rt + (size_t)b * DD * 8;
#pragma unroll
        for (int jj = 0; jj < 4; jj++) {
            int d0 = (lane + 32 * jj) * 4;
            Rt[(d0 + 0) * 8 + k] = v[jj].x * inv;
            Rt[(d0 + 1) * 8 + k] = v[jj].y * inv;
            Rt[(d0 + 2) * 8 + k] = v[jj].z * inv;
            Rt[(d0 + 3) * 8 + k] = v[jj].w * inv;
        }
    }
}

// ---------- Kernel E2+E3 fused: outputs k-major [b][k][h] (R13-exact) ----------
__global__ void __launch_bounds__(256) k_w2ro(const float* __restrict__ Wq,
                                              const float* __restrict__ Wo) {
    __shared__ float4 R_sh[DD * 2];
    int b = blockIdx.y;
    const float4* Rt4 = (const float4*)(g_Rt + (size_t)b * DD * 8);
    for (int i = threadIdx.x; i < DD * 2; i += 256) R_sh[i] = Rt4[i];
    __syncthreads();

    int h = blockIdx.x * 256 + threadIdx.x;  // grid.x = 4
    float acc[8];
#pragma unroll
    for (int k = 0; k < 8; k++) acc[k] = 0.0f;

    if (blockIdx.z == 0) {
        const float4* wq4 = (const float4*)(Wq + (size_t)h * DD);
#pragma unroll 2
        for (int dd = 0; dd < DD / 4; dd++) {
            float4 wv4 = wq4[dd];
            float wv[4] = {wv4.x, wv4.y, wv4.z, wv4.w};
#pragma unroll
            for (int c = 0; c < 4; c++) {
                float4 r0 = R_sh[(dd * 4 + c) * 2];
                float4 r1 = R_sh[(dd * 4 + c) * 2 + 1];
                acc[0] += wv[c] * r0.x; acc[1] += wv[c] * r0.y;
                acc[2] += wv[c] * r0.z; acc[3] += wv[c] * r0.w;
                acc[4] += wv[c] * r1.x; acc[5] += wv[c] * r1.y;
                acc[6] += wv[c] * r1.z; acc[7] += wv[c] * r1.w;
            }
        }
        const float scale = 0.044194173824159216f;  // 1/sqrt(512)
#pragma unroll
        for (int k = 0; k < 8; k++)
            g_W2[((size_t)b * KK + k) * HH + h] = acc[k] * scale;
    } else {
#pragma unroll 4
        for (int d = 0; d < DD; d++) {
            float wo = Wo[(size_t)d * HH + h];
            float4 r0 = R_sh[d * 2];
            float4 r1 = R_sh[d * 2 + 1];
            acc[0] += wo * r0.x; acc[1] += wo * r0.y; acc[2] += wo * r0.z; acc[3] += wo * r0.w;
            acc[4] += wo * r1.x; acc[5] += wo * r1.y; acc[6] += wo * r1.z; acc[7] += wo * r1.w;
        }
#pragma unroll
        for (int k = 0; k < 8; k++)
            g_RO[((size_t)b * KK + k) * HH + h] = acc[k];
    }
}

// ---------- Kernel F (fused, f32x2): logits -> softmax -> out (R13-exact) ----------
__global__ void __launch_bounds__(256) k_attn_out(const float* __restrict__ x,
                                                  float* __restrict__ out) {
    __shared__ float W2s[KK * HH];   // 32KB, [k][h]
    int b = blockIdx.y;
    {
        const float4* src = (const float4*)(g_W2 + (size_t)b * KK * HH);
        float4* dst = (float4*)W2s;
        for (int i = threadIdx.x; i < KK * HH / 4; i += 256) dst[i] = src[i];
    }
    __syncthreads();

    int lane = threadIdx.x & 31, warp = threadIdx.x >> 5;
    int tok0 = blockIdx.x * 16 + warp * 2;
    const ulonglong2* xb0 = (const ulonglong2*)(x + ((size_t)b * SS + tok0) * HH);
    const ulonglong2* xb1 = xb0 + HH / 4;
    const ulonglong2* W2s2 = (const ulonglong2*)W2s;

    unsigned long long acc2[2][8];
#pragma unroll
    for (int k = 0; k < 8; k++) { acc2[0][k] = 0ull; acc2[1][k] = 0ull; }

#pragma unroll 2
    for (int i4 = 0; i4 < 8; i4++) {
        int h4 = lane + 32 * i4;
        ulonglong2 x0 = xb0[h4];
        ulonglong2 x1 = xb1[h4];
#pragma unroll
        for (int k = 0; k < 8; k++) {
            ulonglong2 wv = W2s2[k * (HH / 4) + h4];
            fma2(acc2[0][k], x0.x, wv.x);
            fma2(acc2[0][k], x0.y, wv.y);
            fma2(acc2[1][k], x1.x, wv.x);
            fma2(acc2[1][k], x1.y, wv.y);
        }
    }

    float lp[2][8];
#pragma unroll
    for (int t = 0; t < 2; t++)
#pragma unroll
        for (int k = 0; k < 8; k++) {
            float lo, hi;
            unpack2(acc2[t][k], lo, hi);
            lp[t][k] = lo + hi;
        }
#pragma unroll
    for (int off = 16; off; off >>= 1)
#pragma unroll
        for (int t = 0; t < 2; t++)
#pragma unroll
            for (int k = 0; k < 8; k++)
                lp[t][k] += __shfl_xor_sync(0xffffffffu, lp[t][k], off);

    unsigned long long att2[2][8];
#pragma unroll
    for (int t = 0; t < 2; t++) {
        float m = -3.4e38f;
#pragma unroll
        for (int k = 0; k < 8; k++) m = fmaxf(m, lp[t][k]);
        float s = 0.0f;
        float e[8];
#pragma unroll
        for (int k = 0; k < 8; k++) { e[k] = __expf(lp[t][k] - m); s += e[k]; }
        float inv = 1.0f / s;
#pragma unroll
        for (int k = 0; k < 8; k++) {
            float a = e[k] * inv;
            att2[t][k] = pack2(a, a);
        }
    }

    const ulonglong2* ROb = (const ulonglong2*)(g_RO + (size_t)b * KK * HH);
    ulonglong2* ob0 = (ulonglong2*)(out + ((size_t)b * SS + tok0) * HH);
    ulonglong2* ob1 = ob0 + HH / 4;

#pragma unroll 2
    for (int i4 = 0; i4 < 8; i4++) {
        int h4 = lane + 32 * i4;
        ulonglong2 o0 = xb0[h4];
        ulonglong2 o1 = xb1[h4];
#pragma unroll
        for (int k = 0; k < 8; k++) {
            ulonglong2 rv = __ldg(&ROb[k * (HH / 4) + h4]);
            fma2(o0.x, att2[0][k], rv.x);
            fma2(o0.y, att2[0][k], rv.y);
            fma2(o1.x, att2[1][k], rv.x);
            fma2(o1.y, att2[1][k], rv.y);
        }
        ob0[h4] = o0;
        ob1[h4] = o1;
    }
}

// ---------- launch (scores = 4th launch; R13 structure + R12 scores) ----------
extern "C" void kernel_launch(void* const* d_in, const int* in_sizes, int n_in,
                              void* d_out, int out_size) {
    const float* x   = (const float*)d_in[0];
    const float* mem = (const float*)d_in[1];
    const float* Wq  = (const float*)d_in[2];
    const float* Wo  = (const float*)d_in[3];
    float* out = (float*)d_out;

    k_xpart4  <<<dim3(1, 8, 32), 256>>>(x);
    k_queryp  <<<dim3(2, 8, 8),  256>>>(Wq);
    k_qsum    <<<16,             256>>>();
    k_scores  <<<4096,           256>>>(mem);
    k_topk1   <<<dim3(TKB, 8),   256>>>();
    k_finish  <<<8,              128>>>(mem);
    k_w2ro    <<<dim3(4, 8, 2),  256>>>(Wq, Wo);
    k_attn_out<<<dim3(128, 8),   256>>>(x, out);
}

// round 17
// speedup vs baseline: 1.2321x; 1.0462x over previous
#include <cuda_runtime.h>
#include <math.h>

#define BB 8
#define SS 2048
#define HH 1024
#define NN 262144
#define DD 512
#define KK 8
#define TKB 64

__device__ float g_xpart[32 * BB * HH];     // [z32][b][h], 1MB
__device__ float g_qp[8 * BB * DD];         // [hc][b][d] partial queries
__device__ float g_q[BB * DD];
__device__ float g_scores[BB * NN];
__device__ float g_cand_v[BB * TKB * 8];
__device__ int   g_cand_i[BB * TKB * 8];
__device__ float g_Rt[BB * DD * KK];
__device__ float g_W2[BB * KK * HH];        // [b][k][h] = (Wq @ R^T)^T * 1/sqrt(D)
__device__ float g_RO[BB * KK * HH];        // [b][k][h] = (R @ Wo) k-major

__device__ __forceinline__ void fma2(unsigned long long& d,
                                     unsigned long long a, unsigned long long b) {
    asm("fma.rn.f32x2 %0, %1, %2, %0;" : "+l"(d) : "l"(a), "l"(b));
}
__device__ __forceinline__ void unpack2(unsigned long long v, float& lo, float& hi) {
    unsigned int l, h;
    asm("mov.b64 {%0, %1}, %2;" : "=r"(l), "=r"(h) : "l"(v));
    lo = __uint_as_float(l); hi = __uint_as_float(h);
}
__device__ __forceinline__ unsigned long long pack2(float lo, float hi) {
    unsigned long long r;
    asm("mov.b64 %0, {%1, %2};" : "=l"(r)
        : "r"(__float_as_uint(lo)), "r"(__float_as_uint(hi)));
    return r;
}

// ---------- Kernel A: partial sums of x over S (float4, 32 slots x 64 rows) ----------
__global__ void __launch_bounds__(256) k_xpart4(const float* __restrict__ x) {
    int h4 = threadIdx.x;
    int b = blockIdx.y;
    int z = blockIdx.z;
    const float4* xp = (const float4*)x + ((size_t)b * SS + (size_t)z * 64) * 256 + h4;
    float4 a0 = make_float4(0.f, 0.f, 0.f, 0.f), a1 = a0, a2 = a0, a3 = a0;
    float4 a4 = a0, a5 = a0, a6 = a0, a7 = a0;
#pragma unroll 4
    for (int i = 0; i < 64; i += 8) {
        float4 v0 = xp[(size_t)(i + 0) * 256];
        float4 v1 = xp[(size_t)(i + 1) * 256];
        float4 v2 = xp[(size_t)(i + 2) * 256];
        float4 v3 = xp[(size_t)(i + 3) * 256];
        float4 v4 = xp[(size_t)(i + 4) * 256];
        float4 v5 = xp[(size_t)(i + 5) * 256];
        float4 v6 = xp[(size_t)(i + 6) * 256];
        float4 v7 = xp[(size_t)(i + 7) * 256];
        a0.x += v0.x; a0.y += v0.y; a0.z += v0.z; a0.w += v0.w;
        a1.x += v1.x; a1.y += v1.y; a1.z += v1.z; a1.w += v1.w;
        a2.x += v2.x; a2.y += v2.y; a2.z += v2.z; a2.w += v2.w;
        a3.x += v3.x; a3.y += v3.y; a3.z += v3.z; a3.w += v3.w;
        a4.x += v4.x; a4.y += v4.y; a4.z += v4.z; a4.w += v4.w;
        a5.x += v5.x; a5.y += v5.y; a5.z += v5.z; a5.w += v5.w;
        a6.x += v6.x; a6.y += v6.y; a6.z += v6.z; a6.w += v6.w;
        a7.x += v7.x; a7.y += v7.y; a7.z += v7.z; a7.w += v7.w;
    }
    float4 r;
    r.x = ((a0.x + a1.x) + (a2.x + a3.x)) + ((a4.x + a5.x) + (a6.x + a7.x));
    r.y = ((a0.y + a1.y) + (a2.y + a3.y)) + ((a4.y + a5.y) + (a6.y + a7.y));
    r.z = ((a0.z + a1.z) + (a2.z + a3.z)) + ((a4.z + a5.z) + (a6.z + a7.z));
    r.w = ((a0.w + a1.w) + (a2.w + a3.w)) + ((a4.w + a5.w) + (a6.w + a7.w));
    ((float4*)g_xpart)[(z * BB + b) * 256 + h4] = r;
}

// ---------- Kernel B: partial q over 128-h chunks (128 blocks) ----------
__global__ void __launch_bounds__(256) k_queryp(const float* __restrict__ Wq) {
    __shared__ float xs[128];
    int tid = threadIdx.x;
    int b = blockIdx.y, hc = blockIdx.z;
    if (tid < 128) {
        float s = 0.0f;
#pragma unroll
        for (int z = 0; z < 32; z++)
            s += g_xpart[(z * BB + b) * HH + hc * 128 + tid];
        xs[tid] = s;
    }
    __syncthreads();

    int d = blockIdx.x * 256 + tid;
    float a0 = 0.f, a1 = 0.f, a2 = 0.f, a3 = 0.f, a4 = 0.f, a5 = 0.f, a6 = 0.f, a7 = 0.f;
    const float* wq = Wq + (size_t)(hc * 128) * DD + d;
#pragma unroll 4
    for (int h = 0; h < 128; h += 8) {
        a0 += xs[h + 0] * wq[(size_t)(h + 0) * DD];
        a1 += xs[h + 1] * wq[(size_t)(h + 1) * DD];
        a2 += xs[h + 2] * wq[(size_t)(h + 2) * DD];
        a3 += xs[h + 3] * wq[(size_t)(h + 3) * DD];
        a4 += xs[h + 4] * wq[(size_t)(h + 4) * DD];
        a5 += xs[h + 5] * wq[(size_t)(h + 5) * DD];
        a6 += xs[h + 6] * wq[(size_t)(h + 6) * DD];
        a7 += xs[h + 7] * wq[(size_t)(h + 7) * DD];
    }
    g_qp[(hc * BB + b) * DD + d] = ((a0 + a1) + (a2 + a3)) + ((a4 + a5) + (a6 + a7));
}

// ---------- Kernel B2: q = sum of 8 partials ----------
__global__ void k_qsum() {
    int i = blockIdx.x * 256 + threadIdx.x;
    float s = 0.0f;
#pragma unroll
    for (int hc = 0; hc < 8; hc++) s += g_qp[hc * BB * DD + i];
    g_q[i] = s;
}

// ---------- Kernel C: cosine scores (R12-exact: measured 109.3us x3) ----------
__global__ void __launch_bounds__(256, 3) k_scores(const float* __restrict__ mem) {
    __shared__ ulonglong2 qd[BB * 128];   // [b][d4], 16KB
    __shared__ float s_out[BB * 64];      // 2KB
    int tid = threadIdx.x;
    {
        const ulonglong2* q2 = (const ulonglong2*)g_q;
        for (int i = tid; i < BB * 128; i += 256) qd[i] = q2[i];
    }
    __syncthreads();

    int w = tid >> 5, lane = tid & 31;
    int g = lane >> 3, e = lane & 7;
    int rowloc = w * 8 + g * 2;
    size_t row0 = (size_t)blockIdx.x * 64 + rowloc;
    const ulonglong2* ma_p = (const ulonglong2*)(mem + row0 * DD);
    const ulonglong2* mb_p = (const ulonglong2*)(mem + (row0 + 1) * DD);

    unsigned long long acc2[2][8];
    unsigned long long nrm2[2];
    nrm2[0] = nrm2[1] = 0ull;
#pragma unroll
    for (int b = 0; b < 8; b++) { acc2[0][b] = 0ull; acc2[1][b] = 0ull; }

#pragma unroll 2
    for (int j = 0; j < 16; j++) {
        int d4 = e + 8 * j;
        ulonglong2 ma = ma_p[d4];
        ulonglong2 mb = mb_p[d4];

        fma2(nrm2[0], ma.x, ma.x);
        fma2(nrm2[0], ma.y, ma.y);
        fma2(nrm2[1], mb.x, mb.x);
        fma2(nrm2[1], mb.y, mb.y);
#pragma unroll
        for (int b = 0; b < 8; b++) {
            ulonglong2 qv = qd[b * 128 + d4];
            fma2(acc2[0][b], ma.x, qv.x);
            fma2(acc2[0][b], ma.y, qv.y);
            fma2(acc2[1][b], mb.x, qv.x);
            fma2(acc2[1][b], mb.y, qv.y);
        }
    }

    float acc[2][8], nrm[2];
#pragma unroll
    for (int r = 0; r < 2; r++) {
        float lo, hi;
        unpack2(nrm2[r], lo, hi);
        nrm[r] = lo + hi;
#pragma unroll
        for (int b = 0; b < 8; b++) {
            unpack2(acc2[r][b], lo, hi);
            acc[r][b] = lo + hi;
        }
    }
#pragma unroll
    for (int off = 1; off <= 4; off <<= 1) {
#pragma unroll
        for (int r = 0; r < 2; r++) {
            nrm[r] += __shfl_xor_sync(0xffffffffu, nrm[r], off);
#pragma unroll
            for (int b = 0; b < 8; b++)
                acc[r][b] += __shfl_xor_sync(0xffffffffu, acc[r][b], off);
        }
    }
    if (e == 0) {
#pragma unroll
        for (int r = 0; r < 2; r++) {
            float inv = 1.0f / (sqrtf(nrm[r]) + 1e-8f);
#pragma unroll
            for (int b = 0; b < 8; b++)
                s_out[b * 64 + rowloc + r] = acc[r][b] * inv;
        }
    }
    __syncthreads();
    if (tid < 128) {
        int b = tid >> 4, seg = tid & 15;
        *(float4*)&g_scores[(size_t)b * NN + (size_t)blockIdx.x * 64 + seg * 4] =
            *(const float4*)&s_out[b * 64 + seg * 4];
    }
}

// ---------- Kernel D1: stage-1 top-8 (TKB=64: 16 values/thread, half the merge work) ----------
__global__ void __launch_bounds__(256) k_topk1() {
    __shared__ float sv[256 * 8];
    __shared__ int   si[256 * 8];
    int b = blockIdx.y, blk = blockIdx.x, tid = threadIdx.x;
    int base = blk * (NN / TKB);   // 4096 rows per block
    const float4* s4 = (const float4*)(g_scores + (size_t)b * NN + base);

    float vals[8];
    int idxs[8];
#pragma unroll
    for (int i = 0; i < 8; i++) { vals[i] = -3.4e38f; idxs[i] = 0; }
    float vmin = -3.4e38f;

#pragma unroll
    for (int it = 0; it < 4; it++) {
        int f = tid + it * 256;     // float4 index within slice (0..1023)
        float4 v4 = s4[f];
        int n0 = base + f * 4;
        float vv[4] = {v4.x, v4.y, v4.z, v4.w};
#pragma unroll
        for (int c = 0; c < 4; c++) {
            float v = vv[c];
            if (v > vmin) {
                vals[7] = v; idxs[7] = n0 + c;
#pragma unroll
                for (int p = 7; p >= 1; p--) {
                    if (vals[p] > vals[p - 1]) {
                        float tv = vals[p]; vals[p] = vals[p - 1]; vals[p - 1] = tv;
                        int ti = idxs[p]; idxs[p] = idxs[p - 1]; idxs[p - 1] = ti;
                    }
                }
                vmin = vals[7];
            }
        }
    }
#pragma unroll
    for (int i = 0; i < 8; i++) { sv[tid * 8 + i] = vals[i]; si[tid * 8 + i] = idxs[i]; }

    for (int stride = 128; stride >= 1; stride >>= 1) {
        __syncthreads();
        if (tid < stride) {
            float ov[8]; int oi[8];
            int ia = 0, ib2 = 0;
#pragma unroll
            for (int o = 0; o < 8; o++) {
                float va = sv[tid * 8 + ia];
                float vb = sv[(tid + stride) * 8 + ib2];
                if (va >= vb) { ov[o] = va; oi[o] = si[tid * 8 + ia]; ia++; }
                else          { ov[o] = vb; oi[o] = si[(tid + stride) * 8 + ib2]; ib2++; }
            }
#pragma unroll
            for (int o = 0; o < 8; o++) { sv[tid * 8 + o] = ov[o]; si[tid * 8 + o] = oi[o]; }
        }
    }
    __syncthreads();
    if (tid < 8) {
        g_cand_v[(b * TKB + blk) * 8 + tid] = sv[tid];
        g_cand_i[(b * TKB + blk) * 8 + tid] = si[tid];
    }
}

// ---------- Kernel D2+E1 fused: final merge (64 lists) + gather + normalize ----------
__global__ void __launch_bounds__(128) k_finish(const float* __restrict__ mem) {
    __shared__ float sv[64 * 8];
    __shared__ int   si[64 * 8];
    __shared__ int   s_idx[8];
    int b = blockIdx.x, tid = threadIdx.x;
    if (tid < TKB) {
#pragma unroll
        for (int i = 0; i < 8; i++) {
            sv[tid * 8 + i] = g_cand_v[(b * TKB + tid) * 8 + i];
            si[tid * 8 + i] = g_cand_i[(b * TKB + tid) * 8 + i];
        }
    }
    for (int stride = 32; stride >= 1; stride >>= 1) {
        __syncthreads();
        if (tid < stride) {
            float ov[8]; int oi[8];
            int ia = 0, ib2 = 0;
#pragma unroll
            for (int o = 0; o < 8; o++) {
                float va = sv[tid * 8 + ia];
                float vb = sv[(tid + stride) * 8 + ib2];
                if (va >= vb) { ov[o] = va; oi[o] = si[tid * 8 + ia]; ia++; }
                else          { ov[o] = vb; oi[o] = si[(tid + stride) * 8 + ib2]; ib2++; }
            }
#pragma unroll
            for (int o = 0; o < 8; o++) { sv[tid * 8 + o] = ov[o]; si[tid * 8 + o] = oi[o]; }
        }
    }
    __syncthreads();
    if (tid < 8) s_idx[tid] = si[tid];
    __syncthreads();

    int w = tid >> 5, lane = tid & 31;
#pragma unroll
    for (int kk = 0; kk < 2; kk++) {
        int k = w * 2 + kk;
        int row = s_idx[k];
        const float4* r4 = (const float4*)(mem + (size_t)row * DD);
        float4 v[4];
        float nr = 0.0f;
#pragma unroll
        for (int jj = 0; jj < 4; jj++) {
            v[jj] = r4[lane + 32 * jj];
            nr += v[jj].x * v[jj].x + v[jj].y * v[jj].y
                + v[jj].z * v[jj].z + v[jj].w * v[jj].w;
        }
#pragma unroll
        for (int off = 16; off; off >>= 1)
            nr += __shfl_xor_sync(0xffffffffu, nr, off);
        float inv = 1.0f / (sqrtf(nr) + 1e-8f);
        float* Rt = g_Rt + (size_t)b * DD * 8;
#pragma unroll
        for (int jj = 0; jj < 4; jj++) {
            int d0 = (lane + 32 * jj) * 4;
            Rt[(d0 + 0) * 8 + k] = v[jj].x * inv;
            Rt[(d0 + 1) * 8 + k] = v[jj].y * inv;
            Rt[(d0 + 2) * 8 + k] = v[jj].z * inv;
            Rt[(d0 + 3) * 8 + k] = v[jj].w * inv;
        }
    }
}

// ---------- Kernel E2+E3 fused: outputs k-major [b][k][h] (R13-exact) ----------
__global__ void __launch_bounds__(256) k_w2ro(const float* __restrict__ Wq,
                                              const float* __restrict__ Wo) {
    __shared__ float4 R_sh[DD * 2];
    int b = blockIdx.y;
    const float4* Rt4 = (const float4*)(g_Rt + (size_t)b * DD * 8);
    for (int i = threadIdx.x; i < DD * 2; i += 256) R_sh[i] = Rt4[i];
    __syncthreads();

    int h = blockIdx.x * 256 + threadIdx.x;  // grid.x = 4
    float acc[8];
#pragma unroll
    for (int k = 0; k < 8; k++) acc[k] = 0.0f;

    if (blockIdx.z == 0) {
        const float4* wq4 = (const float4*)(Wq + (size_t)h * DD);
#pragma unroll 2
        for (int dd = 0; dd < DD / 4; dd++) {
            float4 wv4 = wq4[dd];
            float wv[4] = {wv4.x, wv4.y, wv4.z, wv4.w};
#pragma unroll
            for (int c = 0; c < 4; c++) {
                float4 r0 = R_sh[(dd * 4 + c) * 2];
                float4 r1 = R_sh[(dd * 4 + c) * 2 + 1];
                acc[0] += wv[c] * r0.x; acc[1] += wv[c] * r0.y;
                acc[2] += wv[c] * r0.z; acc[3] += wv[c] * r0.w;
                acc[4] += wv[c] * r1.x; acc[5] += wv[c] * r1.y;
                acc[6] += wv[c] * r1.z; acc[7] += wv[c] * r1.w;
            }
        }
        const float scale = 0.044194173824159216f;  // 1/sqrt(512)
#pragma unroll
        for (int k = 0; k < 8; k++)
            g_W2[((size_t)b * KK + k) * HH + h] = acc[k] * scale;
    } else {
#pragma unroll 4
        for (int d = 0; d < DD; d++) {
            float wo = Wo[(size_t)d * HH + h];
            float4 r0 = R_sh[d * 2];
            float4 r1 = R_sh[d * 2 + 1];
            acc[0] += wo * r0.x; acc[1] += wo * r0.y; acc[2] += wo * r0.z; acc[3] += wo * r0.w;
            acc[4] += wo * r1.x; acc[5] += wo * r1.y; acc[6] += wo * r1.z; acc[7] += wo * r1.w;
        }
#pragma unroll
        for (int k = 0; k < 8; k++)
            g_RO[((size_t)b * KK + k) * HH + h] = acc[k];
    }
}

// ---------- Kernel F (fused, f32x2): 4 tokens/warp — halves W2/RO wavefronts per x-byte ----------
__global__ void __launch_bounds__(256) k_attn_out(const float* __restrict__ x,
                                                  float* __restrict__ out) {
    __shared__ float W2s[KK * HH];   // 32KB, [k][h]
    int b = blockIdx.y;
    {
        const float4* src = (const float4*)(g_W2 + (size_t)b * KK * HH);
        float4* dst = (float4*)W2s;
        for (int i = threadIdx.x; i < KK * HH / 4; i += 256) dst[i] = src[i];
    }
    __syncthreads();

    int lane = threadIdx.x & 31, warp = threadIdx.x >> 5;
    int tok0 = blockIdx.x * 32 + warp * 4;   // grid.x = 64, 4 tokens/warp
    const ulonglong2* xb0 = (const ulonglong2*)(x + ((size_t)b * SS + tok0) * HH);
    const ulonglong2* W2s2 = (const ulonglong2*)W2s;

    // ---- pass 1: logits ----
    unsigned long long acc2[4][8];
#pragma unroll
    for (int t = 0; t < 4; t++)
#pragma unroll
        for (int k = 0; k < 8; k++) acc2[t][k] = 0ull;

#pragma unroll 2
    for (int i4 = 0; i4 < 8; i4++) {
        int h4 = lane + 32 * i4;
        ulonglong2 xv[4];
#pragma unroll
        for (int t = 0; t < 4; t++) xv[t] = xb0[t * (HH / 4) + h4];
#pragma unroll
        for (int k = 0; k < 8; k++) {
            ulonglong2 wv = W2s2[k * (HH / 4) + h4];
#pragma unroll
            for (int t = 0; t < 4; t++) {
                fma2(acc2[t][k], xv[t].x, wv.x);
                fma2(acc2[t][k], xv[t].y, wv.y);
            }
        }
    }

    float lp[4][8];
#pragma unroll
    for (int t = 0; t < 4; t++)
#pragma unroll
        for (int k = 0; k < 8; k++) {
            float lo, hi;
            unpack2(acc2[t][k], lo, hi);
            lp[t][k] = lo + hi;
        }
#pragma unroll
    for (int off = 16; off; off >>= 1)
#pragma unroll
        for (int t = 0; t < 4; t++)
#pragma unroll
            for (int k = 0; k < 8; k++)
                lp[t][k] += __shfl_xor_sync(0xffffffffu, lp[t][k], off);

    // ---- softmax in registers ----
    unsigned long long att2[4][8];
#pragma unroll
    for (int t = 0; t < 4; t++) {
        float m = -3.4e38f;
#pragma unroll
        for (int k = 0; k < 8; k++) m = fmaxf(m, lp[t][k]);
        float s = 0.0f;
        float e[8];
#pragma unroll
        for (int k = 0; k < 8; k++) { e[k] = __expf(lp[t][k] - m); s += e[k]; }
        float inv = 1.0f / s;
#pragma unroll
        for (int k = 0; k < 8; k++) {
            float a = e[k] * inv;
            att2[t][k] = pack2(a, a);
        }
    }

    // ---- pass 2: out = x + attn @ RO ----
    const ulonglong2* ROb = (const ulonglong2*)(g_RO + (size_t)b * KK * HH);
    ulonglong2* ob0 = (ulonglong2*)(out + ((size_t)b * SS + tok0) * HH);

#pragma unroll 2
    for (int i4 = 0; i4 < 8; i4++) {
        int h4 = lane + 32 * i4;
        ulonglong2 o[4];
#pragma unroll
        for (int t = 0; t < 4; t++) o[t] = xb0[t * (HH / 4) + h4];
#pragma unroll
        for (int k = 0; k < 8; k++) {
            ulonglong2 rv = __ldg(&ROb[k * (HH / 4) + h4]);
#pragma unroll
            for (int t = 0; t < 4; t++) {
                fma2(o[t].x, att2[t][k], rv.x);
                fma2(o[t].y, att2[t][k], rv.y);
            }
        }
#pragma unroll
        for (int t = 0; t < 4; t++) ob0[t * (HH / 4) + h4] = o[t];
    }
}

// ---------- launch (scores = 4th launch; capture slot sanity-checks scores) ----------
extern "C" void kernel_launch(void* const* d_in, const int* in_sizes, int n_in,
                              void* d_out, int out_size) {
    const float* x   = (const float*)d_in[0];
    const float* mem = (const float*)d_in[1];
    const float* Wq  = (const float*)d_in[2];
    const float* Wo  = (const float*)d_in[3];
    float* out = (float*)d_out;

    k_xpart4  <<<dim3(1, 8, 32), 256>>>(x);
    k_queryp  <<<dim3(2, 8, 8),  256>>>(Wq);
    k_qsum    <<<16,             256>>>();
    k_scores  <<<4096,           256>>>(mem);
    k_topk1   <<<dim3(TKB, 8),   256>>>();
    k_finish  <<<8,              128>>>(mem);
    k_w2ro    <<<dim3(4, 8, 2),  256>>>(Wq, Wo);
    k_attn_out<<<dim3(64, 8),    256>>>(x, out);
}